// round 1
// baseline (speedup 1.0000x reference)
#include <cuda_runtime.h>
#include <cstddef>

#define NPTS 50000
#define C    96
#define G    6
#define S    16
#define CG   16   // C/G

// ---------------- scratch (static device globals; no allocs allowed) --------
__device__ float d_v [NPTS * C];   // v = feat@Wv + bv
__device__ float d_qW[NPTS * G];   // q @ Ww1
__device__ float d_kW[NPTS * G];   // k @ Ww1
__device__ float d_M [C * G];      // Wp2 @ Ww1
__device__ float d_bM[G];          // bp2 @ Ww1

// ---------------- k0: tiny precompute ---------------------------------------
__global__ void k0_pre(const float* __restrict__ Wp2,
                       const float* __restrict__ Ww1,
                       const float* __restrict__ bp2)
{
    int t = threadIdx.x;
    if (t < C * G) {
        int cc = t / G, g = t % G;
        float s = 0.f;
        #pragma unroll 4
        for (int c2 = 0; c2 < C; c2++)
            s = fmaf(Wp2[cc * C + c2], Ww1[c2 * G + g], s);
        d_M[t] = s;
    }
    if (t < G) {
        float s = 0.f;
        for (int c2 = 0; c2 < C; c2++)
            s = fmaf(bp2[c2], Ww1[c2 * G + t], s);
        d_bM[t] = s;
    }
}

// ---------------- k1: QKV projections + qW/kW reduction ----------------------
// block: 256 threads, tile 128 points. shared: featS(128x96) WS(96x96) tmpS(128x96)
#define K1_TILE 128
#define K1_THREADS 256
#define K1_SMEM ((K1_TILE*C + C*C + K1_TILE*C) * 4)

__global__ __launch_bounds__(K1_THREADS)
void k1_qkv(const float* __restrict__ feat,
            const float* __restrict__ Wq, const float* __restrict__ bq,
            const float* __restrict__ gq, const float* __restrict__ betaq,
            const float* __restrict__ Wk, const float* __restrict__ bk,
            const float* __restrict__ gk, const float* __restrict__ betak,
            const float* __restrict__ Wv, const float* __restrict__ bv,
            const float* __restrict__ Ww1)
{
    extern __shared__ float sh[];
    float* featS = sh;                   // 128*96
    float* WS    = sh + K1_TILE * C;     // 96*96
    float* tmpS  = WS + C * C;           // 128*96

    const int tid = threadIdx.x;
    const int n0  = blockIdx.x * K1_TILE;
    const float RS = rsqrtf(1.0f + 1e-5f);

    for (int i = tid; i < K1_TILE * C; i += K1_THREADS) {
        int n = n0 + i / C;
        featS[i] = (n < NPTS) ? feat[(size_t)n0 * C + i] : 0.0f;
    }

    const int tx = tid & 31, ty = tid >> 5;   // c = tx + 32*cc ; p = ty*16 + pp

    const float* Wm[3]  = {Wq, Wk, Wv};
    const float* bm[3]  = {bq, bk, bv};
    const float* gm[2]  = {gq, gk};
    const float* btm[2] = {betaq, betak};

    for (int m = 0; m < 3; m++) {
        __syncthreads();                       // protects WS/tmpS reuse
        for (int i = tid; i < C * C; i += K1_THREADS) WS[i] = Wm[m][i];
        __syncthreads();

        float acc[16][3];
        #pragma unroll
        for (int pp = 0; pp < 16; pp++)
            acc[pp][0] = acc[pp][1] = acc[pp][2] = 0.f;

        #pragma unroll 2
        for (int k = 0; k < C; k++) {
            float b0 = WS[k * C + tx];
            float b1 = WS[k * C + tx + 32];
            float b2 = WS[k * C + tx + 64];
            #pragma unroll
            for (int pp = 0; pp < 16; pp++) {
                float a = featS[(ty * 16 + pp) * C + k];
                acc[pp][0] = fmaf(a, b0, acc[pp][0]);
                acc[pp][1] = fmaf(a, b1, acc[pp][1]);
                acc[pp][2] = fmaf(a, b2, acc[pp][2]);
            }
        }

        if (m < 2) {
            float bb[3], sc[3], bt[3];
            #pragma unroll
            for (int cc = 0; cc < 3; cc++) {
                int ch = tx + 32 * cc;
                bb[cc] = bm[m][ch];
                sc[cc] = gm[m][ch] * RS;
                bt[cc] = btm[m][ch];
            }
            #pragma unroll
            for (int pp = 0; pp < 16; pp++) {
                int p = ty * 16 + pp;
                #pragma unroll
                for (int cc = 0; cc < 3; cc++) {
                    float v = fmaf(acc[pp][cc] + bb[cc], sc[cc], bt[cc]);
                    tmpS[p * C + tx + 32 * cc] = fmaxf(v, 0.f);
                }
            }
            __syncthreads();
            float* dst = (m == 0) ? d_qW : d_kW;
            #pragma unroll
            for (int r = 0; r < 3; r++) {
                int t = tid + r * K1_THREADS;          // 0..767 = 128*6
                int p = t / G, g = t % G;
                int n = n0 + p;
                if (n < NPTS) {
                    float s = 0.f;
                    #pragma unroll 4
                    for (int c2 = 0; c2 < C; c2++)
                        s = fmaf(tmpS[p * C + c2], __ldg(&Ww1[c2 * G + g]), s);
                    dst[(size_t)n * G + g] = s;
                }
            }
        } else {
            #pragma unroll
            for (int cc = 0; cc < 3; cc++) {
                int ch = tx + 32 * cc;
                float bvc = bv[ch];
                #pragma unroll
                for (int pp = 0; pp < 16; pp++) {
                    int n = n0 + ty * 16 + pp;
                    if (n < NPTS) d_v[(size_t)n * C + ch] = acc[pp][cc] + bvc;
                }
            }
        }
    }
}

// ---------------- k2: per-point attention ------------------------------------
// 8 points ("pods") per block, 96 threads per pod = 768 threads.
#define PTS 8
#define K2_THREADS (PTS * C)
#define POD_F 2608   // floats per pod
// layout: Wp2T 96*100 | MT 6*96 | cst 68 | pods
#define K2_SMEM_F (C * 100 + G * C + 68 + PTS * POD_F)
#define K2_SMEM (K2_SMEM_F * 4)

__global__ __launch_bounds__(K2_THREADS, 1)
void k2_attn(const float* __restrict__ coord,
             const int*   __restrict__ refidx,
             const float* __restrict__ Wp1, const float* __restrict__ bp1,
             const float* __restrict__ gp,  const float* __restrict__ betap,
             const float* __restrict__ Wp2, const float* __restrict__ bp2,
             const float* __restrict__ bw1, const float* __restrict__ gw,
             const float* __restrict__ betaw,
             const float* __restrict__ Ww2, const float* __restrict__ bw2,
             float* __restrict__ out)
{
    extern __shared__ float sh[];
    float* Wp2T = sh;                      // [c_out][100] : Wp2T[co*100+ci] = Wp2[ci][co]
    float* MT   = Wp2T + C * 100;          // [g][96]
    float* cst  = MT + G * C;              // Ww2(36) bw2(6) bw1(6) gw(6) betaw(6) bM(6)
    float* podb = cst + 68;

    const int tid = threadIdx.x;
    const int pod = tid / C;
    const int c   = tid % C;
    const int n   = blockIdx.x * PTS + pod;     // 50000 = 6250*8, no tail

    float* P    = podb + pod * POD_F;
    float* hs   = P;            // [16][100]
    float* Hs   = P + 1600;     // [6][100]
    float* ws   = P + 2200;     // [16][8] (pad)
    float* us   = P + 2328;     // [16][6]
    float* wls  = P + 2424;     // [16][6]
    float* pos  = P + 2520;     // [16][4]
    float* wsum = P + 2584;     // [8]
    int*   js   = (int*)(P + 2592);  // [16]

    const float RS = rsqrtf(1.0f + 1e-5f);

    // P0: stage transposed Wp2, MT, tiny consts
    for (int i = tid; i < C * C; i += K2_THREADS) {
        int ci = i / C, co = i % C;
        Wp2T[co * 100 + ci] = Wp2[i];
    }
    for (int i = tid; i < C * G; i += K2_THREADS) {
        int cc = i / G, g = i % G;
        MT[g * C + cc] = d_M[i];
    }
    if      (tid < 36) cst[tid] = Ww2[tid];
    else if (tid < 42) cst[tid] = bw2[tid - 36];
    else if (tid < 48) cst[tid] = bw1[tid - 42];
    else if (tid < 54) cst[tid] = gw[tid - 48];
    else if (tid < 60) cst[tid] = betaw[tid - 54];
    else if (tid < 66) cst[tid] = d_bM[tid - 60];
    // P1: neighbour indices
    if (c < S) js[c] = refidx[(size_t)n * S + c];
    __syncthreads();

    // P2: relative positions + ws pad zeros
    if (c < 48) {
        int s = c / 3, d = c % 3;
        pos[s * 4 + d] = __ldg(&coord[(size_t)js[s] * 3 + d]) - __ldg(&coord[(size_t)n * 3 + d]);
    } else if (c >= 64 && c < 80) {
        int s = c - 64;
        ws[s * 8 + 6] = 0.f; ws[s * 8 + 7] = 0.f;
    }
    __syncthreads();

    // P3: h[s][c] = relu(bn(pos@Wp1 + bp1))
    float w10 = __ldg(&Wp1[0 * C + c]);
    float w11 = __ldg(&Wp1[1 * C + c]);
    float w12 = __ldg(&Wp1[2 * C + c]);
    float bp1c = __ldg(&bp1[c]);
    float sp  = __ldg(&gp[c]) * RS;
    float btp = __ldg(&betap[c]);
    float hr[16];
    #pragma unroll
    for (int s = 0; s < 16; s++) {
        float hv = fmaf(pos[s*4], w10, fmaf(pos[s*4+1], w11, fmaf(pos[s*4+2], w12, bp1c)));
        hv = fmaxf(fmaf(hv, sp, btp), 0.0f);
        hr[s] = hv;
        hs[s * 100 + c] = hv;
    }
    __syncthreads();

    // P4: u[s][g] = relu(bn(kW[j]-qW[n] + h@M + bM + bw1))
    {
        int s = c / 6, g = c % 6;
        float acc = 0.f;
        #pragma unroll
        for (int c4 = 0; c4 < C; c4 += 4) {
            float4 hv = *(const float4*)&hs[s * 100 + c4];
            float4 mv = *(const float4*)&MT[g * C + c4];
            acc = fmaf(hv.x, mv.x, fmaf(hv.y, mv.y, fmaf(hv.z, mv.z, fmaf(hv.w, mv.w, acc))));
        }
        float kq = __ldg(&d_kW[(size_t)js[s] * G + g]) - __ldg(&d_qW[(size_t)n * G + g]);
        float t = kq + acc + cst[60 + g] + cst[42 + g];        // + bM + bw1
        float u = fmaxf(fmaf(t, cst[48 + g] * RS, cst[54 + g]), 0.0f);
        us[s * 6 + g] = u;
    }
    __syncthreads();

    // P5: logits = u @ Ww2 + bw2
    {
        int s = c / 6, g2 = c % 6;
        float lg = cst[36 + g2];
        #pragma unroll
        for (int g = 0; g < 6; g++) lg = fmaf(us[s * 6 + g], cst[g * 6 + g2], lg);
        wls[s * 6 + g2] = lg;
    }
    __syncthreads();

    // P6: softmax over s per g (6 threads/pod), then mask
    if (c < 6) {
        int g = c;
        float m = -1e30f;
        #pragma unroll
        for (int s = 0; s < 16; s++) m = fmaxf(m, wls[s * 6 + g]);
        float e[16]; float sum = 0.f;
        #pragma unroll
        for (int s = 0; s < 16; s++) { e[s] = expf(wls[s * 6 + g] - m); sum += e[s]; }
        float inv = 1.0f / sum;
        float accw = 0.f;
        #pragma unroll
        for (int s = 0; s < 16; s++) {
            int jp1 = js[s] + 1;
            float msk = (jp1 > 0) ? 1.0f : ((jp1 < 0) ? -1.0f : 0.0f);
            float w = e[s] * inv * msk;
            ws[s * 8 + g] = w;
            accw += w;
        }
        wsum[g] = accw;
    }
    __syncthreads();

    // P7: H[g][c] = sum_s w[s][g]*h[s][c]; vsum = sum_s w[s][gc]*v[j_s][c]
    int gc = c >> 4;
    float vj[16];
    #pragma unroll
    for (int s = 0; s < 16; s++) vj[s] = __ldg(&d_v[(size_t)js[s] * C + c]);
    float Hg[6] = {0,0,0,0,0,0};
    float vsum = 0.f;
    #pragma unroll
    for (int s = 0; s < 16; s++) {
        float4 wa = *(const float4*)&ws[s * 8];
        float4 wb = *(const float4*)&ws[s * 8 + 4];
        Hg[0] = fmaf(wa.x, hr[s], Hg[0]);
        Hg[1] = fmaf(wa.y, hr[s], Hg[1]);
        Hg[2] = fmaf(wa.z, hr[s], Hg[2]);
        Hg[3] = fmaf(wa.w, hr[s], Hg[3]);
        Hg[4] = fmaf(wb.x, hr[s], Hg[4]);
        Hg[5] = fmaf(wb.y, hr[s], Hg[5]);
        float wg = (gc == 0) ? wa.x : (gc == 1) ? wa.y : (gc == 2) ? wa.z
                 : (gc == 3) ? wa.w : (gc == 4) ? wb.x : wb.y;
        vsum = fmaf(wg, vj[s], vsum);
    }
    #pragma unroll
    for (int g = 0; g < 6; g++) Hs[g * 100 + c] = Hg[g];
    __syncthreads();

    // P8: out[c] = vsum + bp2[c]*wsum[gc] + H[gc] . Wp2[:,c]
    float acc = fmaf(__ldg(&bp2[c]), wsum[gc], vsum);
    #pragma unroll
    for (int c4 = 0; c4 < C; c4 += 4) {
        float4 hh = *(const float4*)&Hs[gc * 100 + c4];
        float4 wv = *(const float4*)&Wp2T[c * 100 + c4];
        acc = fmaf(hh.x, wv.x, fmaf(hh.y, wv.y, fmaf(hh.z, wv.z, fmaf(hh.w, wv.w, acc))));
    }
    out[(size_t)n * C + c] = acc;
}

// ---------------- host launcher ---------------------------------------------
extern "C" void kernel_launch(void* const* d_in, const int* in_sizes, int n_in,
                              void* d_out, int out_size)
{
    // Auto-detect input ordering: dict order puts reference_index (N*S=800000 ints)
    // at slot 2; signature order puts Wq (9216 floats) there.
    bool dict = (in_sizes[2] == NPTS * S);

    const float* feat  = (const float*)d_in[0];
    const float* coord = (const float*)d_in[1];
    const int*   ref   = (const int*)d_in[dict ? 2 : 24];
    int wb = dict ? 3 : 2;
    const float* Wq    = (const float*)d_in[wb + 0];
    const float* bq    = (const float*)d_in[wb + 1];
    const float* gq    = (const float*)d_in[wb + 2];
    const float* betaq = (const float*)d_in[wb + 3];
    const float* Wk    = (const float*)d_in[wb + 4];
    const float* bk    = (const float*)d_in[wb + 5];
    const float* gk    = (const float*)d_in[wb + 6];
    const float* betak = (const float*)d_in[wb + 7];
    const float* Wv    = (const float*)d_in[wb + 8];
    const float* bv    = (const float*)d_in[wb + 9];
    const float* Wp1   = (const float*)d_in[wb + 10];
    const float* bp1   = (const float*)d_in[wb + 11];
    const float* gp    = (const float*)d_in[wb + 12];
    const float* betap = (const float*)d_in[wb + 13];
    const float* Wp2   = (const float*)d_in[wb + 14];
    const float* bp2   = (const float*)d_in[wb + 15];
    const float* Ww1   = (const float*)d_in[wb + 16];
    const float* bw1   = (const float*)d_in[wb + 17];
    const float* gw    = (const float*)d_in[wb + 18];
    const float* betaw = (const float*)d_in[wb + 19];
    const float* Ww2   = (const float*)d_in[wb + 20];
    const float* bw2   = (const float*)d_in[wb + 21];
    float* out = (float*)d_out;

    cudaFuncSetAttribute(k1_qkv,  cudaFuncAttributeMaxDynamicSharedMemorySize, K1_SMEM);
    cudaFuncSetAttribute(k2_attn, cudaFuncAttributeMaxDynamicSharedMemorySize, K2_SMEM);

    k0_pre<<<1, 576>>>(Wp2, Ww1, bp2);
    k1_qkv<<<(NPTS + K1_TILE - 1) / K1_TILE, K1_THREADS, K1_SMEM>>>(
        feat, Wq, bq, gq, betaq, Wk, bk, gk, betak, Wv, bv, Ww1);
    k2_attn<<<NPTS / PTS, K2_THREADS, K2_SMEM>>>(
        coord, ref, Wp1, bp1, gp, betap, Wp2, bp2, bw1, gw, betaw, Ww2, bw2, out);
}

// round 2
// speedup vs baseline: 1.7644x; 1.7644x over previous
#include <cuda_runtime.h>
#include <cstddef>

#define NPTS 50000
#define C    96
#define G    6
#define S    16

// ---------------- scratch (static device globals) ----------------------------
__device__ float d_v   [NPTS * C];   // v = feat@Wv + bv
__device__ float d_qW  [NPTS * G];   // relu(bn(q)) @ Ww1
__device__ float d_kW  [NPTS * G];   // relu(bn(k)) @ Ww1
__device__ float d_MT  [G * C];      // MT[g][cc] = (Wp2 @ Ww1)[cc][g]
__device__ float d_bM  [G];          // bp2 @ Ww1
__device__ float d_Wp2T[C * C];      // [co][ci] = Wp2[ci][co]

// ---------------- k1: QKV projections + qW/kW + fused precompute -------------
#define K1_TILE 128
#define K1_THREADS 256
// featS 128*100 | WST 96*100 | tmpS 128*100 | Ww1T 6*100
#define K1_SMEM_F (K1_TILE*100 + C*100 + K1_TILE*100 + G*100)
#define K1_SMEM (K1_SMEM_F * 4)

__global__ __launch_bounds__(K1_THREADS)
void k1_qkv(const float* __restrict__ feat,
            const float* __restrict__ Wq, const float* __restrict__ bq,
            const float* __restrict__ gq, const float* __restrict__ betaq,
            const float* __restrict__ Wk, const float* __restrict__ bk,
            const float* __restrict__ gk, const float* __restrict__ betak,
            const float* __restrict__ Wv, const float* __restrict__ bv,
            const float* __restrict__ Ww1,
            const float* __restrict__ Wp2, const float* __restrict__ bp2)
{
    const int tid = threadIdx.x;

    // ---- fused precompute block (replaces k0) ----
    if (blockIdx.x == gridDim.x - 1) {
        for (int i = tid; i < C * C; i += K1_THREADS) {
            int co = i / C, ci = i % C;
            d_Wp2T[i] = __ldg(&Wp2[ci * C + co]);
        }
        for (int i = tid; i < G * C; i += K1_THREADS) {
            int g = i / C, cc = i % C;
            float s = 0.f;
            #pragma unroll 4
            for (int c2 = 0; c2 < C; c2++)
                s = fmaf(__ldg(&Wp2[cc * C + c2]), __ldg(&Ww1[c2 * G + g]), s);
            d_MT[i] = s;
        }
        if (tid < G) {
            float s = 0.f;
            for (int c2 = 0; c2 < C; c2++)
                s = fmaf(__ldg(&bp2[c2]), __ldg(&Ww1[c2 * G + tid]), s);
            d_bM[tid] = s;
        }
        return;
    }

    extern __shared__ float sh[];
    float* featS = sh;                        // [p][k] stride 100
    float* WST   = sh + K1_TILE * 100;        // [c][k] stride 100
    float* tmpS  = WST + C * 100;             // [p][c] stride 100
    float* Ww1T  = tmpS + K1_TILE * 100;      // [g][c] stride 100

    const int n0 = blockIdx.x * K1_TILE;
    const float RS = rsqrtf(1.0f + 1e-5f);

    // stage featS (float4, coalesced) + Ww1T
    for (int i = tid; i < K1_TILE * 24; i += K1_THREADS) {
        int p = i / 24, kq = (i % 24) * 4;
        int n = n0 + p;
        float4 vv = (n < NPTS) ? *(const float4*)&feat[(size_t)n * C + kq]
                               : make_float4(0.f, 0.f, 0.f, 0.f);
        *(float4*)&featS[p * 100 + kq] = vv;
    }
    for (int i = tid; i < C * G; i += K1_THREADS) {
        int c2 = i / G, g = i % G;
        Ww1T[g * 100 + c2] = Ww1[i];
    }

    const int tx = tid & 31, ty = tid >> 5;   // c = tx+32*cc ; p = ty*16+pp

    for (int m = 0; m < 3; m++) {
        __syncthreads();
        const float* W = (m == 0) ? Wq : (m == 1) ? Wk : Wv;
        // stage transposed weight tile (float4 reads)
        for (int i = tid; i < C * 24; i += K1_THREADS) {
            int k = i / 24, cq = (i % 24) * 4;
            float4 w = *(const float4*)&W[k * C + cq];
            WST[(cq + 0) * 100 + k] = w.x;
            WST[(cq + 1) * 100 + k] = w.y;
            WST[(cq + 2) * 100 + k] = w.z;
            WST[(cq + 3) * 100 + k] = w.w;
        }
        __syncthreads();

        float acc[16][3];
        #pragma unroll
        for (int pp = 0; pp < 16; pp++)
            acc[pp][0] = acc[pp][1] = acc[pp][2] = 0.f;

        #pragma unroll 2
        for (int k4 = 0; k4 < C; k4 += 4) {
            float4 b0 = *(const float4*)&WST[tx * 100 + k4];
            float4 b1 = *(const float4*)&WST[(tx + 32) * 100 + k4];
            float4 b2 = *(const float4*)&WST[(tx + 64) * 100 + k4];
            #pragma unroll
            for (int pp = 0; pp < 16; pp++) {
                float4 a = *(const float4*)&featS[(ty * 16 + pp) * 100 + k4];
                acc[pp][0] = fmaf(a.x, b0.x, fmaf(a.y, b0.y, fmaf(a.z, b0.z, fmaf(a.w, b0.w, acc[pp][0]))));
                acc[pp][1] = fmaf(a.x, b1.x, fmaf(a.y, b1.y, fmaf(a.z, b1.z, fmaf(a.w, b1.w, acc[pp][1]))));
                acc[pp][2] = fmaf(a.x, b2.x, fmaf(a.y, b2.y, fmaf(a.z, b2.z, fmaf(a.w, b2.w, acc[pp][2]))));
            }
        }

        if (m < 2) {
            const float* bb_ = (m == 0) ? bq : bk;
            const float* gg_ = (m == 0) ? gq : gk;
            const float* bt_ = (m == 0) ? betaq : betak;
            float bb[3], sc[3], bt[3];
            #pragma unroll
            for (int cc = 0; cc < 3; cc++) {
                int ch = tx + 32 * cc;
                bb[cc] = bb_[ch];
                sc[cc] = gg_[ch] * RS;
                bt[cc] = bt_[ch];
            }
            #pragma unroll
            for (int pp = 0; pp < 16; pp++) {
                int p = ty * 16 + pp;
                #pragma unroll
                for (int cc = 0; cc < 3; cc++) {
                    float v = fmaf(acc[pp][cc] + bb[cc], sc[cc], bt[cc]);
                    tmpS[p * 100 + tx + 32 * cc] = fmaxf(v, 0.f);
                }
            }
            __syncthreads();
            float* dst = (m == 0) ? d_qW : d_kW;
            #pragma unroll
            for (int r = 0; r < 3; r++) {
                int t = tid + r * K1_THREADS;    // 768 = 128*6
                int p = t / G, g = t % G;
                int n = n0 + p;
                if (n < NPTS) {
                    float s = 0.f;
                    #pragma unroll
                    for (int c4 = 0; c4 < C; c4 += 4) {
                        float4 hv = *(const float4*)&tmpS[p * 100 + c4];
                        float4 wv = *(const float4*)&Ww1T[g * 100 + c4];
                        s = fmaf(hv.x, wv.x, fmaf(hv.y, wv.y, fmaf(hv.z, wv.z, fmaf(hv.w, wv.w, s))));
                    }
                    dst[(size_t)n * G + g] = s;
                }
            }
        } else {
            float bb[3];
            #pragma unroll
            for (int cc = 0; cc < 3; cc++) bb[cc] = bv[tx + 32 * cc];
            #pragma unroll
            for (int pp = 0; pp < 16; pp++) {
                int p = ty * 16 + pp;
                #pragma unroll
                for (int cc = 0; cc < 3; cc++)
                    tmpS[p * 100 + tx + 32 * cc] = acc[pp][cc] + bb[cc];
            }
            __syncthreads();
            // float4 repacked stores
            for (int i = tid; i < K1_TILE * 24; i += K1_THREADS) {
                int p = i / 24, cq = (i % 24) * 4;
                int n = n0 + p;
                if (n < NPTS)
                    *(float4*)&d_v[(size_t)n * C + cq] = *(const float4*)&tmpS[p * 100 + cq];
            }
        }
    }
}

// ---------------- k2: per-point attention ------------------------------------
#define PTS 4
#define K2_THREADS (PTS * C)      // 384
#define POD_F 2608
// Wp2T 96*100 | MTs 6*100 | cst 68 | pods
#define K2_SMEM_F (C*100 + G*100 + 68 + PTS*POD_F)
#define K2_SMEM (K2_SMEM_F * 4)

__device__ __forceinline__ void podbar(int pod) {
    asm volatile("bar.sync %0, 96;" :: "r"(pod + 1) : "memory");
}

__global__ __launch_bounds__(K2_THREADS, 2)
void k2_attn(const float* __restrict__ coord,
             const int*   __restrict__ refidx,
             const float* __restrict__ Wp1, const float* __restrict__ bp1,
             const float* __restrict__ gp,  const float* __restrict__ betap,
             const float* __restrict__ bp2,
             const float* __restrict__ bw1, const float* __restrict__ gw,
             const float* __restrict__ betaw,
             const float* __restrict__ Ww2, const float* __restrict__ bw2,
             float* __restrict__ out)
{
    extern __shared__ float sh[];
    float* Wp2T = sh;                  // [co][ci] stride 100
    float* MTs  = sh + C * 100;        // [g][cc] stride 100
    float* cst  = MTs + G * 100;       // Ww2(36) bw2(6) bw1(6) gw(6) betaw(6) bM(6)
    float* podb = cst + 68;

    const int tid = threadIdx.x;
    const int pod = tid / C;
    const int c   = tid % C;
    const int n   = blockIdx.x * PTS + pod;   // 50000 = 12500*4

    float* P    = podb + pod * POD_F;
    float* hs   = P;            // [16][100]
    float* Hs   = P + 1600;     // [6][100]
    float* ws   = P + 2200;     // [16][8] (pad)
    float* us   = P + 2328;     // [16][6]
    float* wls  = P + 2424;     // [16][6]
    float* pos  = P + 2520;     // [16][4]
    float* wsum = P + 2584;     // [8]
    int*   js   = (int*)(P + 2592);  // [16]

    const float RS = rsqrtf(1.0f + 1e-5f);

    // ---- staging (independent of P1/P2, one combined sync) ----
    for (int i = tid; i < C * 24; i += K2_THREADS) {
        int co = i / 24, ciq = (i % 24) * 4;
        *(float4*)&Wp2T[co * 100 + ciq] = *(const float4*)&d_Wp2T[co * C + ciq];
    }
    for (int i = tid; i < G * C; i += K2_THREADS)
        MTs[(i / C) * 100 + (i % C)] = d_MT[i];
    if      (tid < 36) cst[tid] = Ww2[tid];
    else if (tid < 42) cst[tid] = bw2[tid - 36];
    else if (tid < 48) cst[tid] = bw1[tid - 42];
    else if (tid < 54) cst[tid] = gw[tid - 48];
    else if (tid < 60) cst[tid] = betaw[tid - 54];
    else if (tid < 66) cst[tid] = d_bM[tid - 60];

    // P1/P2: indices + relative positions (redundant refidx loads avoid a bar)
    if (c < S) js[c] = refidx[(size_t)n * S + c];
    if (c < 48) {
        int s = c / 3, d = c % 3;
        int j = __ldg(&refidx[(size_t)n * S + s]);
        pos[s * 4 + d] = __ldg(&coord[(size_t)j * 3 + d]) - __ldg(&coord[(size_t)n * 3 + d]);
    } else if (c < 64) {
        int s = c - 48;
        ws[s * 8 + 6] = 0.f; ws[s * 8 + 7] = 0.f;
    }
    __syncthreads();

    // P3: h[s][c] = relu(bn(pos@Wp1 + bp1))
    float w10 = __ldg(&Wp1[c]);
    float w11 = __ldg(&Wp1[C + c]);
    float w12 = __ldg(&Wp1[2 * C + c]);
    float bp1c = __ldg(&bp1[c]);
    float sp   = __ldg(&gp[c]) * RS;
    float btp  = __ldg(&betap[c]);
    float hr[16];
    #pragma unroll
    for (int s = 0; s < 16; s++) {
        float hv = fmaf(pos[s*4], w10, fmaf(pos[s*4+1], w11, fmaf(pos[s*4+2], w12, bp1c)));
        hv = fmaxf(fmaf(hv, sp, btp), 0.0f);
        hr[s] = hv;
        hs[s * 100 + c] = hv;
    }
    podbar(pod);

    // P4: u[s][g] = relu(bn(kW[j]-qW[n] + h@M + bM + bw1))
    {
        int s = c / 6, g = c % 6;
        float acc = 0.f;
        #pragma unroll
        for (int c4 = 0; c4 < C; c4 += 4) {
            float4 hv = *(const float4*)&hs[s * 100 + c4];
            float4 mv = *(const float4*)&MTs[g * 100 + c4];
            acc = fmaf(hv.x, mv.x, fmaf(hv.y, mv.y, fmaf(hv.z, mv.z, fmaf(hv.w, mv.w, acc))));
        }
        float kq = __ldg(&d_kW[(size_t)js[s] * G + g]) - __ldg(&d_qW[(size_t)n * G + g]);
        float t = kq + acc + cst[60 + g] + cst[42 + g];        // + bM + bw1
        us[s * 6 + g] = fmaxf(fmaf(t, cst[48 + g] * RS, cst[54 + g]), 0.0f);
    }
    podbar(pod);

    // P5: logits = u @ Ww2 + bw2
    {
        int s = c / 6, g2 = c % 6;
        float lg = cst[36 + g2];
        #pragma unroll
        for (int g = 0; g < 6; g++) lg = fmaf(us[s * 6 + g], cst[g * 6 + g2], lg);
        wls[s * 6 + g2] = lg;
    }
    podbar(pod);

    // P6: softmax over s per g (6 threads/pod), recompute-exp to save regs
    if (c < 6) {
        int g = c;
        float m = -1e30f;
        #pragma unroll
        for (int s = 0; s < 16; s++) m = fmaxf(m, wls[s * 6 + g]);
        float sum = 0.f;
        #pragma unroll
        for (int s = 0; s < 16; s++) sum += __expf(wls[s * 6 + g] - m);
        float inv = 1.0f / sum;
        float accw = 0.f;
        #pragma unroll
        for (int s = 0; s < 16; s++) {
            int jp1 = js[s] + 1;
            float msk = (float)((jp1 > 0) - (jp1 < 0));
            float w = __expf(wls[s * 6 + g] - m) * inv * msk;
            ws[s * 8 + g] = w;
            accw += w;
        }
        wsum[g] = accw;
    }
    podbar(pod);

    // P7: H[g][c] = sum_s w[s][g]*h[s][c]; vsum = sum_s w[s][gc]*v[j_s][c]
    int gc = c >> 4;
    float Hg[6] = {0,0,0,0,0,0};
    float vsum = 0.f;
    #pragma unroll
    for (int s = 0; s < 16; s++) {
        float4 wa = *(const float4*)&ws[s * 8];
        float4 wb = *(const float4*)&ws[s * 8 + 4];
        float h = hr[s];
        Hg[0] = fmaf(wa.x, h, Hg[0]);
        Hg[1] = fmaf(wa.y, h, Hg[1]);
        Hg[2] = fmaf(wa.z, h, Hg[2]);
        Hg[3] = fmaf(wa.w, h, Hg[3]);
        Hg[4] = fmaf(wb.x, h, Hg[4]);
        Hg[5] = fmaf(wb.y, h, Hg[5]);
        float wg = ws[s * 8 + gc];
        vsum = fmaf(wg, __ldg(&d_v[(size_t)js[s] * C + c]), vsum);
    }
    #pragma unroll
    for (int g = 0; g < 6; g++) Hs[g * 100 + c] = Hg[g];
    podbar(pod);

    // P8: out[c] = vsum + bp2[c]*wsum[gc] + H[gc] . Wp2[:,c]
    float acc = fmaf(__ldg(&bp2[c]), wsum[gc], vsum);
    #pragma unroll
    for (int c4 = 0; c4 < C; c4 += 4) {
        float4 hh = *(const float4*)&Hs[gc * 100 + c4];
        float4 wv = *(const float4*)&Wp2T[c * 100 + c4];
        acc = fmaf(hh.x, wv.x, fmaf(hh.y, wv.y, fmaf(hh.z, wv.z, fmaf(hh.w, wv.w, acc))));
    }
    out[(size_t)n * C + c] = acc;
}

// ---------------- host launcher ---------------------------------------------
extern "C" void kernel_launch(void* const* d_in, const int* in_sizes, int n_in,
                              void* d_out, int out_size)
{
    bool dict = (in_sizes[2] == NPTS * S);

    const float* feat  = (const float*)d_in[0];
    const float* coord = (const float*)d_in[1];
    const int*   ref   = (const int*)d_in[dict ? 2 : 24];
    int wb = dict ? 3 : 2;
    const float* Wq    = (const float*)d_in[wb + 0];
    const float* bq    = (const float*)d_in[wb + 1];
    const float* gq    = (const float*)d_in[wb + 2];
    const float* betaq = (const float*)d_in[wb + 3];
    const float* Wk    = (const float*)d_in[wb + 4];
    const float* bk    = (const float*)d_in[wb + 5];
    const float* gk    = (const float*)d_in[wb + 6];
    const float* betak = (const float*)d_in[wb + 7];
    const float* Wv    = (const float*)d_in[wb + 8];
    const float* bv    = (const float*)d_in[wb + 9];
    const float* Wp1   = (const float*)d_in[wb + 10];
    const float* bp1   = (const float*)d_in[wb + 11];
    const float* gp    = (const float*)d_in[wb + 12];
    const float* betap = (const float*)d_in[wb + 13];
    const float* Wp2   = (const float*)d_in[wb + 14];
    const float* bp2   = (const float*)d_in[wb + 15];
    const float* Ww1   = (const float*)d_in[wb + 16];
    const float* bw1   = (const float*)d_in[wb + 17];
    const float* gw    = (const float*)d_in[wb + 18];
    const float* betaw = (const float*)d_in[wb + 19];
    const float* Ww2   = (const float*)d_in[wb + 20];
    const float* bw2   = (const float*)d_in[wb + 21];
    float* out = (float*)d_out;

    cudaFuncSetAttribute(k1_qkv,  cudaFuncAttributeMaxDynamicSharedMemorySize, K1_SMEM);
    cudaFuncSetAttribute(k2_attn, cudaFuncAttributeMaxDynamicSharedMemorySize, K2_SMEM);

    int k1_blocks = (NPTS + K1_TILE - 1) / K1_TILE + 1;   // +1 precompute block
    k1_qkv<<<k1_blocks, K1_THREADS, K1_SMEM>>>(
        feat, Wq, bq, gq, betaq, Wk, bk, gk, betak, Wv, bv, Ww1, Wp2, bp2);
    k2_attn<<<NPTS / PTS, K2_THREADS, K2_SMEM>>>(
        coord, ref, Wp1, bp1, gp, betap, bp2, bw1, gw, betaw, Ww2, bw2, out);
}